// round 6
// baseline (speedup 1.0000x reference)
#include <cuda_runtime.h>
#include <cstdint>

#define NNODES 4096
#define NG     8
#define MPER   512
#define NW     16   // 512 bits = 16 uint32 words per row (block-local columns)
#define NBLK   128

// Scratch (no allocation allowed -> device globals)
__device__ uint32_t g_mask[NNODES * NW];   // A bitmask, block-local columns
__device__ int      g_deg[NNODES];
__device__ float    g_feat[7 * NNODES];    // feature-major [7][4096]
__device__ unsigned g_bar  = 0;            // grid barrier (monotonic per launch)
__device__ unsigned g_exit = 0;            // exit counter for reset

__device__ __forceinline__ void grid_barrier(unsigned target) {
    __syncthreads();
    if (threadIdx.x == 0) {
        __threadfence();
        atomicAdd(&g_bar, 1u);
        while (*(volatile unsigned*)&g_bar < target) { }
        __threadfence();
    }
    __syncthreads();
}

__device__ __forceinline__ float warp_sum(float v) {
    #pragma unroll
    for (int o = 16; o; o >>= 1) v += __shfl_down_sync(0xffffffffu, v, o);
    return v;
}

// ---------------------------------------------------------------------------
// ONE kernel, 128 co-resident blocks x 512 threads, 3 phases + grid barriers.
// ---------------------------------------------------------------------------
__global__ void __launch_bounds__(512) fused_kernel(const float* __restrict__ A,
                                                    float* __restrict__ out) {
    __shared__ uint32_t smask[MPER * NW];   // 32 KB (rowstats)
    __shared__ int      sdeg[MPER];
    __shared__ uint32_t sdegp[MPER / 4];
    __shared__ float    sh[MPER];           // stats
    __shared__ float    r1[16], r2[16], r3[16], r4[16];
    __shared__ float    bcast;

    int b = blockIdx.x;
    int t = threadIdx.x;
    int warp = t >> 5, lane = t & 31;

    // ======================= Phase 0: pack =======================
    {
        int wid = b * 16 + warp;               // 0..2047
        int n0  = wid * 2;
        int g   = n0 >> 9;
        long base0 = (long)n0 * NNODES + ((long)g << 9);
        long base1 = base0 + NNODES;

        float4 a[2][4];
        #pragma unroll
        for (int c = 0; c < 4; c++) {
            a[0][c] = *reinterpret_cast<const float4*>(A + base0 + c * 128 + 4 * lane);
            a[1][c] = *reinterpret_cast<const float4*>(A + base1 + c * 128 + 4 * lane);
        }

        #pragma unroll
        for (int r = 0; r < 2; r++) {
            int n = n0 + r;
            int deg = 0;
            #pragma unroll
            for (int c = 0; c < 4; c++) {
                float4 v = a[r][c];
                uint32_t nib = (uint32_t)(v.x != 0.0f)
                             | ((uint32_t)(v.y != 0.0f) << 1)
                             | ((uint32_t)(v.z != 0.0f) << 2)
                             | ((uint32_t)(v.w != 0.0f) << 3);
                deg += __popc(nib);
                uint32_t w = nib;
                w |= __shfl_down_sync(0xffffffffu, w, 1, 8) << 4;
                w |= __shfl_down_sync(0xffffffffu, w, 2, 8) << 8;
                w |= __shfl_down_sync(0xffffffffu, w, 4, 8) << 16;
                if ((lane & 7) == 0)
                    g_mask[n * NW + c * 4 + (lane >> 3)] = w;
            }
            #pragma unroll
            for (int o = 16; o; o >>= 1) deg += __shfl_down_sync(0xffffffffu, deg, o);
            if (lane == 0) g_deg[n] = deg;
        }
    }

    grid_barrier(NBLK);

    // ======================= Phase 1: rowstats =======================
    {
        int g   = b >> 4;
        int sub = b & 15;
        int lo  = g << 9;

        const uint4* src = reinterpret_cast<const uint4*>(&g_mask[lo * NW]);
        uint4*       dst = reinterpret_cast<uint4*>(smask);
        #pragma unroll
        for (int i = 0; i < 4; i++) dst[t + 512 * i] = src[t + 512 * i];
        sdeg[t] = g_deg[lo + t];
        __syncthreads();
        if (t < 128) {
            sdegp[t] = (uint32_t)sdeg[4 * t]
                     | ((uint32_t)sdeg[4 * t + 1] << 8)
                     | ((uint32_t)sdeg[4 * t + 2] << 16)
                     | ((uint32_t)sdeg[4 * t + 3] << 24);
        }
        __syncthreads();

        int half = lane >> 4;
        int l    = lane & 15;
        int nl   = sub * 32 + warp * 2 + half;

        uint32_t mw = smask[nl * NW + l];
        uint32_t diagbit = (l == (nl >> 5)) ? (1u << (nl & 31)) : 0u;
        mw |= diagbit;

        uint32_t m2 = 0;
        int f4r = 0;

        #pragma unroll 1
        for (int w2 = 0; w2 < NW; w2++) {
            uint32_t bits = __shfl_sync(0xffffffffu, mw, (lane & 16) | w2);
            while (bits) {
                int k = w2 * 32 + __ffs(bits) - 1;
                bits &= bits - 1;
                uint32_t rk = smask[k * NW + l];
                m2 |= rk;
                f4r += __popc(rk & mw);
            }
        }

        int m2cnt = __popc(m2);
        uint32_t aw = mw & ~diagbit;
        int f2num = 0;
        {
            uint32_t bits = aw;
            while (bits) {
                int bb = __ffs(bits) - 1;
                bits &= bits - 1;
                f2num += sdeg[l * 32 + bb];
            }
        }
        int m2deg;
        {
            const uint4* sp4 = reinterpret_cast<const uint4*>(sdegp);
            uint4 q0 = sp4[l * 2], q1 = sp4[l * 2 + 1];
            uint32_t dq[8] = {q0.x, q0.y, q0.z, q0.w, q1.x, q1.y, q1.z, q1.w};
            unsigned acc = 0u;
            #pragma unroll
            for (int j = 0; j < 8; j++) {
                uint32_t spread = (((m2 >> (4 * j)) & 0xFu) * 0x00204081u) & 0x01010101u;
                acc = __dp4a(spread, dq[j], acc);
            }
            m2deg = (int)acc;
        }

        #pragma unroll
        for (int o = 8; o; o >>= 1) {
            f4r   += __shfl_down_sync(0xffffffffu, f4r,   o, 16);
            m2cnt += __shfl_down_sync(0xffffffffu, m2cnt, o, 16);
            m2deg += __shfl_down_sync(0xffffffffu, m2deg, o, 16);
            f2num += __shfl_down_sync(0xffffffffu, f2num, o, 16);
        }

        if (l == 0) {
            int   n   = lo + nl;
            float deg = (float)sdeg[nl];
            float f1v = 0.0f;
            if (deg > 1.0f) f1v = 2.0f * ((float)f4r - deg) / (deg * (deg - 1.0f));
            float f2v = (deg > 0.0f) ? (float)f2num / deg : 0.0f;
            float f4v = 0.5f * (float)f4r;
            float f5v = (float)m2deg - 2.0f * (float)f4r;
            float f6v = (float)m2cnt - deg - 1.0f;
            g_feat[0 * NNODES + n] = deg;
            g_feat[1 * NNODES + n] = f1v;
            g_feat[2 * NNODES + n] = f2v;
            g_feat[4 * NNODES + n] = f4v;
            g_feat[5 * NNODES + n] = f5v;
            g_feat[6 * NNODES + n] = f6v;
        }
    }

    grid_barrier(2 * NBLK);

    // ======================= Phase 2: stats (blocks 0..55) =======================
    if (b < 56) {
        int f = b >> 3;          // 0..6
        int g = b & 7;           // 0..7
        int lo = g << 9;

        float x;
        if (f == 3) {
            // f3 = mean over neighbors of f1
            sh[t] = g_feat[1 * NNODES + lo + t];
            __syncthreads();
            int n = lo + t;
            float s = 0.0f;
            const uint4* rm = reinterpret_cast<const uint4*>(&g_mask[n * NW]);
            #pragma unroll
            for (int q = 0; q < 4; q++) {
                uint4 u = rm[q];
                uint32_t ws[4] = {u.x, u.y, u.z, u.w};
                #pragma unroll
                for (int j = 0; j < 4; j++) {
                    uint32_t bits = ws[j];
                    int base = (q * 4 + j) * 32;
                    while (bits) {
                        int v = base + __ffs(bits) - 1;
                        bits &= bits - 1;
                        s += sh[v];
                    }
                }
            }
            float deg = (float)g_deg[n];
            x = (deg > 0.0f) ? s / deg : 0.0f;
            __syncthreads();
        } else {
            x = g_feat[f * NNODES + lo + t];
        }

        // mean
        float s = warp_sum(x);
        if (lane == 0) r1[warp] = s;
        __syncthreads();
        if (warp == 0) {
            float v = (lane < 16) ? r1[lane] : 0.0f;
            #pragma unroll
            for (int o = 8; o; o >>= 1) v += __shfl_down_sync(0xffffffffu, v, o);
            if (lane == 0) bcast = v * (1.0f / MPER);
        }
        __syncthreads();
        float mean = bcast;

        // central moments
        float c  = x - mean;
        float c2 = c * c, c3 = c2 * c, c4 = c2 * c2;
        float s2 = warp_sum(c2), s3 = warp_sum(c3), s4 = warp_sum(c4);
        if (lane == 0) { r2[warp] = s2; r3[warp] = s3; r4[warp] = s4; }
        __syncthreads();
        if (warp == 0) {
            float v2 = (lane < 16) ? r2[lane] : 0.0f;
            float v3 = (lane < 16) ? r3[lane] : 0.0f;
            float v4 = (lane < 16) ? r4[lane] : 0.0f;
            #pragma unroll
            for (int o = 8; o; o >>= 1) {
                v2 += __shfl_down_sync(0xffffffffu, v2, o);
                v3 += __shfl_down_sync(0xffffffffu, v3, o);
                v4 += __shfl_down_sync(0xffffffffu, v4, o);
            }
            if (lane == 0) {
                float m2 = v2 * (1.0f / MPER);
                float m3 = v3 * (1.0f / MPER);
                float m4 = v4 * (1.0f / MPER);
                float eps = 1e-4f;
                float sd   = sqrtf(m2);
                float skew = m3 / fmaxf(m2 * sd, eps);
                float kurt = m4 / fmaxf(m2 * m2, eps);
                out[g * 35 +  0 + f] = mean;
                out[g * 35 + 14 + f] = sd;
                out[g * 35 + 21 + f] = skew;
                out[g * 35 + 28 + f] = kurt;
            }
        }

        // lower median: hybrid bitonic sort
        #pragma unroll 1
        for (int k = 2; k <= MPER; k <<= 1) {
            bool dirUp = ((t & k) == 0);
            #pragma unroll 1
            for (int j = k >> 1; j >= 32; j >>= 1) {
                __syncthreads();
                sh[t] = x;
                __syncthreads();
                float other = sh[t ^ j];
                bool amLow = ((t & j) == 0);
                x = (dirUp == amLow) ? fminf(x, other) : fmaxf(x, other);
            }
            int j0 = (k >> 1 < 16) ? (k >> 1) : 16;
            #pragma unroll 1
            for (int j = j0; j >= 1; j >>= 1) {
                float other = __shfl_xor_sync(0xffffffffu, x, j);
                bool amLow = ((t & j) == 0);
                x = (dirUp == amLow) ? fminf(x, other) : fmaxf(x, other);
            }
        }
        if (t == (MPER - 1) / 2) out[g * 35 + 7 + f] = x;
    }

    // ======================= Exit: reset barrier state =======================
    __syncthreads();
    if (t == 0) {
        unsigned v = atomicAdd(&g_exit, 1u);
        if (v == NBLK - 1) {                 // last block out resets for next launch
            *(volatile unsigned*)&g_bar  = 0u;
            *(volatile unsigned*)&g_exit = 0u;
            __threadfence();
        }
    }
}

// ---------------------------------------------------------------------------
extern "C" void kernel_launch(void* const* d_in, const int* in_sizes, int n_in,
                              void* d_out, int out_size) {
    const float* A = (const float*)d_in[0];
    float* out = (float*)d_out;
    fused_kernel<<<NBLK, 512>>>(A, out);
}